// round 5
// baseline (speedup 1.0000x reference)
#include <cuda_runtime.h>
#include <math.h>

#define Bc 4
#define Sc 1024
#define Dc 1024
#define Ec 8
#define DEc 128
#define SCALEF (1.0f/32.0f)   // 1/sqrt(1024)

typedef unsigned long long u64;

// ---- packed dual-fp32 helpers (sm_100+ fma.rn.f32x2) ----
__device__ __forceinline__ void ffma2(u64 &d, u64 a, u64 b) {
    asm("fma.rn.f32x2 %0, %1, %2, %0;" : "+l"(d) : "l"(a), "l"(b));
}
__device__ __forceinline__ u64 pk2(float x, float y) {
    u64 r; asm("mov.b64 %0, {%1, %2};" : "=l"(r) : "f"(x), "f"(y)); return r;
}
__device__ __forceinline__ float hadd2(u64 a) {
    float lo, hi; asm("mov.b64 {%0, %1}, %2;" : "=f"(lo), "=f"(hi) : "l"(a));
    return lo + hi;
}

// -------- scratch (static __device__, allocation-free) --------
__device__ float g_S[(size_t)Ec*Bc*Sc*Sc];   // 134 MB unnormalized exp scores
__device__ float g_L[Ec*Bc*Sc];              // row sumexp
__device__ float g_attn[(size_t)Bc*Sc*Sc];   // 16 MB combined attention
__device__ int   g_sel[Bc*Ec];               // top-2 selection mask

// ============================================================
// K0: top-2 expert selection (first-occurrence ties, like lax.top_k)
// ============================================================
__global__ void k_top2(const float* __restrict__ rp) {
    int b = threadIdx.x;
    if (b >= Bc) return;
    for (int e = 0; e < Ec; e++) g_sel[b*Ec + e] = 0;
    int i1 = 0; float v1 = rp[b*Ec];
    for (int e = 1; e < Ec; e++) {
        float v = rp[b*Ec + e];
        if (v > v1) { v1 = v; i1 = e; }
    }
    int i2 = -1; float v2 = -INFINITY;
    for (int e = 0; e < Ec; e++) {
        if (e == i1) continue;
        float v = rp[b*Ec + e];
        if (v > v2) { v2 = v; i2 = e; }
    }
    g_sel[b*Ec + i1] = 1;
    g_sel[b*Ec + i2] = 1;
}

// ============================================================
// K1: per masked (e,b): ONE pass. p = exp(QK/32) (no max subtraction:
// scores ~N(0,0.125), overflow impossible). Stream p to g_S, row sums to g_L.
// ============================================================
__global__ void k_score(const float* __restrict__ Qg, const float* __restrict__ Kg,
                        const int* __restrict__ em) {
    const int e = blockIdx.z, b = blockIdx.y, s0 = blockIdx.x * 64;
    if (em[e*Bc + b] == 0) return;

    extern __shared__ float sm[];
    float* sQ = sm;                 // 64*132
    float* sK = sm + 64*132;        // 64*132
    float* sS = sm + 2*64*132;      // 64*68
    float* sL = sS + 64*68;         // 64

    const int tid = threadIdx.x;
    const int tx = tid & 15, ty = tid >> 4;

    const float* Qb = Qg + ((size_t)b*Sc + s0)*Dc + e*DEc;
    for (int l = tid; l < 2048; l += 256) {
        int r = l >> 5, c4 = l & 31;
        *(float4*)(sQ + r*132 + c4*4) = *(const float4*)(Qb + (size_t)r*Dc + c4*4);
    }
    if (tid < 64) sL[tid] = 0.f;

    float* Srow = g_S + (((size_t)e*Bc + b)*Sc + s0)*Sc;

    for (int t0 = 0; t0 < Sc; t0 += 64) {
        __syncthreads();
        const float* Kb = Kg + ((size_t)b*Sc + t0)*Dc + e*DEc;
        for (int l = tid; l < 2048; l += 256) {
            int r = l >> 5, c4 = l & 31;
            *(float4*)(sK + r*132 + c4*4) = *(const float4*)(Kb + (size_t)r*Dc + c4*4);
        }
        __syncthreads();

        u64 acc2[4][4] = {};
        #pragma unroll 2
        for (int d = 0; d < DEc; d += 4) {
            float4 av[4], kv[4];
            #pragma unroll
            for (int i = 0; i < 4; i++) av[i] = *(const float4*)(sQ + (ty + 16*i)*132 + d);
            #pragma unroll
            for (int j = 0; j < 4; j++) kv[j] = *(const float4*)(sK + (tx + 16*j)*132 + d);
            u64 aL[4], aH[4], bL[4], bH[4];
            #pragma unroll
            for (int i = 0; i < 4; i++) { aL[i] = pk2(av[i].x, av[i].y); aH[i] = pk2(av[i].z, av[i].w); }
            #pragma unroll
            for (int j = 0; j < 4; j++) { bL[j] = pk2(kv[j].x, kv[j].y); bH[j] = pk2(kv[j].z, kv[j].w); }
            #pragma unroll
            for (int i = 0; i < 4; i++)
                #pragma unroll
                for (int j = 0; j < 4; j++) {
                    ffma2(acc2[i][j], aL[i], bL[j]);
                    ffma2(acc2[i][j], aH[i], bH[j]);
                }
        }
        #pragma unroll
        for (int i = 0; i < 4; i++)
            #pragma unroll
            for (int j = 0; j < 4; j++)
                sS[(ty + 16*i)*68 + tx + 16*j] = __expf(hadd2(acc2[i][j])*SCALEF);
        __syncthreads();

        {
            int row = tid >> 2, sub = tid & 3;
            float ssum = 0.f;
            #pragma unroll
            for (int c = 0; c < 16; c++) ssum += sS[row*68 + sub*16 + c];
            ssum += __shfl_xor_sync(0xffffffffu, ssum, 1);
            ssum += __shfl_xor_sync(0xffffffffu, ssum, 2);
            if (sub == 0) sL[row] += ssum;
        }
        for (int l = tid; l < 1024; l += 256) {
            int r = l >> 4, c4 = l & 15;
            *(float4*)(Srow + (size_t)r*Sc + t0 + c4*4) = *(const float4*)(sS + r*68 + c4*4);
        }
    }
    __syncthreads();
    if (tid < 64) g_L[(e*Bc + b)*Sc + s0 + tid] = sL[tid];
}

// ============================================================
// K2: attn[b,s,:] = sum_e mask[e,b] * g_S[e,b,s,:] / L[e,b,s]
// ============================================================
__global__ void k_combine(const int* __restrict__ em) {
    const int bs = blockIdx.x;
    const int b = bs >> 10, s = bs & 1023;
    const int tid = threadIdx.x;

    float4 acc = make_float4(0.f, 0.f, 0.f, 0.f);
    #pragma unroll
    for (int e = 0; e < Ec; e++) {
        if (em[e*Bc + b] == 0) continue;
        int eb = e*Bc + b;
        float invL = 1.0f / g_L[(size_t)eb*Sc + s];
        float4 v = *(const float4*)(g_S + (((size_t)eb*Sc + s)*Sc) + tid*4);
        acc.x += v.x*invL; acc.y += v.y*invL;
        acc.z += v.z*invL; acc.w += v.w*invL;
    }
    *(float4*)(g_attn + ((size_t)b*Sc + s)*Sc + tid*4) = acc;
}

// ============================================================
// K3: out = attn @ V-slice. 64x64 output tile per block, thread does
// 4 rows x 4 cols. sA stored [row][t] so A reads are LDS.128 over t.
// grid (B, S/64, E*2). FMA/LDS-byte = 0.5 (vs 0.33 before).
// ============================================================
__global__ void k_out(const float* __restrict__ Vg, float* __restrict__ out) {
    const int b = blockIdx.x, s0 = blockIdx.y*64;
    const int e = blockIdx.z >> 1, half = blockIdx.z & 1;
    const int col0 = e*DEc + half*64;
    float* O = out + ((size_t)b*Sc + s0)*Dc + col0;
    const int tid = threadIdx.x;

    if (g_sel[b*Ec + e] == 0) {
        float4 z = make_float4(0.f, 0.f, 0.f, 0.f);
        for (int l = tid; l < 1024; l += 256) {   // 64 rows x 16 float4
            int r = l >> 4, c4 = l & 15;
            *(float4*)(O + (size_t)r*Dc + c4*4) = z;
        }
        return;
    }

    extern __shared__ float smo[];
    float* sA = smo;            // 64 rows x 68 (t index)
    float* sV = smo + 64*68;    // 64 t x 68 (col index)

    const int tx = tid & 15, ty = tid >> 4;   // cols 4*tx, rows ty+16i
    float4 acc[4] = {make_float4(0,0,0,0), make_float4(0,0,0,0),
                     make_float4(0,0,0,0), make_float4(0,0,0,0)};

    for (int t0 = 0; t0 < Sc; t0 += 64) {
        __syncthreads();
        const float* Ab = g_attn + ((size_t)b*Sc + s0)*Sc + t0;
        for (int l = tid; l < 1024; l += 256) {   // A tile: [row][t]
            int r = l >> 4, c4 = l & 15;
            *(float4*)(sA + r*68 + c4*4) = *(const float4*)(Ab + (size_t)r*Sc + c4*4);
        }
        const float* Vb = Vg + ((size_t)b*Sc + t0)*Dc + col0;
        for (int l = tid; l < 1024; l += 256) {   // V tile: [t][col]
            int r = l >> 4, c4 = l & 15;
            *(float4*)(sV + r*68 + c4*4) = *(const float4*)(Vb + (size_t)r*Dc + c4*4);
        }
        __syncthreads();

        #pragma unroll 4
        for (int t = 0; t < 64; t += 4) {
            float4 a4[4];
            #pragma unroll
            for (int i = 0; i < 4; i++)
                a4[i] = *(const float4*)(sA + (ty + 16*i)*68 + t);
            #pragma unroll
            for (int k = 0; k < 4; k++) {
                float4 v = *(const float4*)(sV + (t + k)*68 + 4*tx);
                float a0 = (k==0)?a4[0].x:(k==1)?a4[0].y:(k==2)?a4[0].z:a4[0].w;
                float a1 = (k==0)?a4[1].x:(k==1)?a4[1].y:(k==2)?a4[1].z:a4[1].w;
                float a2 = (k==0)?a4[2].x:(k==1)?a4[2].y:(k==2)?a4[2].z:a4[2].w;
                float a3 = (k==0)?a4[3].x:(k==1)?a4[3].y:(k==2)?a4[3].z:a4[3].w;
                acc[0].x += a0*v.x; acc[0].y += a0*v.y; acc[0].z += a0*v.z; acc[0].w += a0*v.w;
                acc[1].x += a1*v.x; acc[1].y += a1*v.y; acc[1].z += a1*v.z; acc[1].w += a1*v.w;
                acc[2].x += a2*v.x; acc[2].y += a2*v.y; acc[2].z += a2*v.z; acc[2].w += a2*v.w;
                acc[3].x += a3*v.x; acc[3].y += a3*v.y; acc[3].z += a3*v.z; acc[3].w += a3*v.w;
            }
        }
    }

    #pragma unroll
    for (int i = 0; i < 4; i++)
        *(float4*)(O + (size_t)(ty + 16*i)*Dc + 4*tx) = acc[i];
}

// ============================================================
extern "C" void kernel_launch(void* const* d_in, const int* in_sizes, int n_in,
                              void* d_out, int out_size) {
    const float* Q  = (const float*)d_in[0];
    const float* K  = (const float*)d_in[1];
    const float* V  = (const float*)d_in[2];
    const float* rp = (const float*)d_in[3];
    const int*   em = (const int*)  d_in[4];
    float* out = (float*)d_out;

    const int smem_score = (2*64*132 + 64*68 + 64) * 4;   // ~85 KB
    const int smem_out   = (2*64*68) * 4;                 // ~34.8 KB
    cudaFuncSetAttribute(k_score, cudaFuncAttributeMaxDynamicSharedMemorySize, smem_score);
    cudaFuncSetAttribute(k_out,   cudaFuncAttributeMaxDynamicSharedMemorySize, smem_out);

    k_top2   <<<1, 32>>>(rp);
    k_score  <<<dim3(Sc/64, Bc, Ec), 256, smem_score>>>(Q, K, em);
    k_combine<<<Bc*Sc, 256>>>(em);
    k_out    <<<dim3(Bc, Sc/64, Ec*2), 256, smem_out>>>(V, out);
}

// round 6
// speedup vs baseline: 1.7364x; 1.7364x over previous
#include <cuda_runtime.h>
#include <math.h>

#define Bc 4
#define Sc 1024
#define Dc 1024
#define Ec 8
#define DEc 128
#define SCALEF (1.0f/32.0f)   // 1/sqrt(1024)

typedef unsigned long long u64;

// ---- packed dual-fp32 helpers (sm_100+ fma.rn.f32x2) ----
__device__ __forceinline__ void ffma2(u64 &d, u64 a, u64 b) {
    asm("fma.rn.f32x2 %0, %1, %2, %0;" : "+l"(d) : "l"(a), "l"(b));
}
__device__ __forceinline__ u64 pk2(float x, float y) {
    u64 r; asm("mov.b64 %0, {%1, %2};" : "=l"(r) : "f"(x), "f"(y)); return r;
}
__device__ __forceinline__ float hadd2(u64 a) {
    float lo, hi; asm("mov.b64 {%0, %1}, %2;" : "=f"(lo), "=f"(hi) : "l"(a));
    return lo + hi;
}

// -------- scratch (static __device__, allocation-free) --------
__device__ float g_S[(size_t)Ec*Bc*Sc*Sc];   // 134 MB unnormalized exp scores
__device__ float g_L[Ec*Bc*Sc];              // row sumexp
__device__ float g_attn[(size_t)Bc*Sc*Sc];   // 16 MB combined attention
__device__ int   g_slot[Bc][2];              // compacted top-2 expert ids

// ============================================================
// K0: top-2 expert selection (first-occurrence ties, like lax.top_k)
// ============================================================
__global__ void k_top2(const float* __restrict__ rp) {
    int b = threadIdx.x;
    if (b >= Bc) return;
    int i1 = 0; float v1 = rp[b*Ec];
    for (int e = 1; e < Ec; e++) {
        float v = rp[b*Ec + e];
        if (v > v1) { v1 = v; i1 = e; }
    }
    int i2 = -1; float v2 = -INFINITY;
    for (int e = 0; e < Ec; e++) {
        if (e == i1) continue;
        float v = rp[b*Ec + e];
        if (v > v2) { v2 = v; i2 = e; }
    }
    g_slot[b][0] = i1;
    g_slot[b][1] = i2;
}

// ============================================================
// Kz: zero the whole output (unselected expert slices stay zero).
// ============================================================
__global__ void k_zero(float* __restrict__ out) {
    size_t i = ((size_t)blockIdx.x*256 + threadIdx.x)*4;
    *(float4*)(out + i) = make_float4(0.f, 0.f, 0.f, 0.f);
}

// ============================================================
// K1: per masked (e,b): ONE pass. p = exp(QK/32) (no max subtraction:
// scores ~N(0,0.125), overflow impossible). Stream p to g_S, row sums to g_L.
// ============================================================
__global__ void k_score(const float* __restrict__ Qg, const float* __restrict__ Kg,
                        const int* __restrict__ em) {
    const int e = blockIdx.z, b = blockIdx.y, s0 = blockIdx.x * 64;
    if (em[e*Bc + b] == 0) return;

    extern __shared__ float sm[];
    float* sQ = sm;                 // 64*132
    float* sK = sm + 64*132;        // 64*132
    float* sS = sm + 2*64*132;      // 64*68
    float* sL = sS + 64*68;         // 64

    const int tid = threadIdx.x;
    const int tx = tid & 15, ty = tid >> 4;

    const float* Qb = Qg + ((size_t)b*Sc + s0)*Dc + e*DEc;
    for (int l = tid; l < 2048; l += 256) {
        int r = l >> 5, c4 = l & 31;
        *(float4*)(sQ + r*132 + c4*4) = *(const float4*)(Qb + (size_t)r*Dc + c4*4);
    }
    if (tid < 64) sL[tid] = 0.f;

    float* Srow = g_S + (((size_t)e*Bc + b)*Sc + s0)*Sc;

    for (int t0 = 0; t0 < Sc; t0 += 64) {
        __syncthreads();
        const float* Kb = Kg + ((size_t)b*Sc + t0)*Dc + e*DEc;
        for (int l = tid; l < 2048; l += 256) {
            int r = l >> 5, c4 = l & 31;
            *(float4*)(sK + r*132 + c4*4) = *(const float4*)(Kb + (size_t)r*Dc + c4*4);
        }
        __syncthreads();

        u64 acc2[4][4] = {};
        #pragma unroll 2
        for (int d = 0; d < DEc; d += 4) {
            float4 av[4], kv[4];
            #pragma unroll
            for (int i = 0; i < 4; i++) av[i] = *(const float4*)(sQ + (ty + 16*i)*132 + d);
            #pragma unroll
            for (int j = 0; j < 4; j++) kv[j] = *(const float4*)(sK + (tx + 16*j)*132 + d);
            u64 aL[4], aH[4], bL[4], bH[4];
            #pragma unroll
            for (int i = 0; i < 4; i++) { aL[i] = pk2(av[i].x, av[i].y); aH[i] = pk2(av[i].z, av[i].w); }
            #pragma unroll
            for (int j = 0; j < 4; j++) { bL[j] = pk2(kv[j].x, kv[j].y); bH[j] = pk2(kv[j].z, kv[j].w); }
            #pragma unroll
            for (int i = 0; i < 4; i++)
                #pragma unroll
                for (int j = 0; j < 4; j++) {
                    ffma2(acc2[i][j], aL[i], bL[j]);
                    ffma2(acc2[i][j], aH[i], bH[j]);
                }
        }
        #pragma unroll
        for (int i = 0; i < 4; i++)
            #pragma unroll
            for (int j = 0; j < 4; j++)
                sS[(ty + 16*i)*68 + tx + 16*j] = __expf(hadd2(acc2[i][j])*SCALEF);
        __syncthreads();

        {
            int row = tid >> 2, sub = tid & 3;
            float ssum = 0.f;
            #pragma unroll
            for (int c = 0; c < 16; c++) ssum += sS[row*68 + sub*16 + c];
            ssum += __shfl_xor_sync(0xffffffffu, ssum, 1);
            ssum += __shfl_xor_sync(0xffffffffu, ssum, 2);
            if (sub == 0) sL[row] += ssum;
        }
        for (int l = tid; l < 1024; l += 256) {
            int r = l >> 4, c4 = l & 15;
            *(float4*)(Srow + (size_t)r*Sc + t0 + c4*4) = *(const float4*)(sS + r*68 + c4*4);
        }
    }
    __syncthreads();
    if (tid < 64) g_L[(e*Bc + b)*Sc + s0 + tid] = sL[tid];
}

// ============================================================
// K2: attn[b,s,:] = sum_e mask[e,b] * g_S[e,b,s,:] / L[e,b,s]
// ============================================================
__global__ void k_combine(const int* __restrict__ em) {
    const int bs = blockIdx.x;
    const int b = bs >> 10, s = bs & 1023;
    const int tid = threadIdx.x;

    float4 acc = make_float4(0.f, 0.f, 0.f, 0.f);
    #pragma unroll
    for (int e = 0; e < Ec; e++) {
        if (em[e*Bc + b] == 0) continue;
        int eb = e*Bc + b;
        float invL = 1.0f / g_L[(size_t)eb*Sc + s];
        float4 v = *(const float4*)(g_S + (((size_t)eb*Sc + s)*Sc) + tid*4);
        acc.x += v.x*invL; acc.y += v.y*invL;
        acc.z += v.z*invL; acc.w += v.w*invL;
    }
    *(float4*)(g_attn + ((size_t)b*Sc + s)*Sc + tid*4) = acc;
}

// ============================================================
// K3: out = attn @ V-slice for SELECTED experts only (compacted grid,
// every block works). 32-row x 64-col tile, thread = 2 rows x 4 cols.
// grid (B, S/32, 4): z = slot*2 + half. A stored [row][t] (float4 over t).
// ============================================================
__global__ void k_out(const float* __restrict__ Vg, float* __restrict__ out) {
    const int b = blockIdx.x, s0 = blockIdx.y*32;
    const int slot = blockIdx.z >> 1, half = blockIdx.z & 1;
    const int e = g_slot[b][slot];
    const int col0 = e*DEc + half*64;
    float* O = out + ((size_t)b*Sc + s0)*Dc + col0;
    const int tid = threadIdx.x;

    extern __shared__ float smo[];
    float* sA = smo;            // 32 rows x 68 (t index)
    float* sV = smo + 32*68;    // 64 t x 68 (col index)

    const int tx = tid & 15, ty = tid >> 4;   // cols 4*tx, rows ty / ty+16
    float4 acc0 = make_float4(0.f,0.f,0.f,0.f);
    float4 acc1 = make_float4(0.f,0.f,0.f,0.f);

    for (int t0 = 0; t0 < Sc; t0 += 64) {
        __syncthreads();
        const float* Ab = g_attn + ((size_t)b*Sc + s0)*Sc + t0;
        for (int l = tid; l < 512; l += 256) {    // 32 rows x 16 float4
            int r = l >> 4, c4 = l & 15;
            *(float4*)(sA + r*68 + c4*4) = *(const float4*)(Ab + (size_t)r*Sc + c4*4);
        }
        const float* Vb = Vg + ((size_t)b*Sc + t0)*Dc + col0;
        for (int l = tid; l < 1024; l += 256) {   // 64 t x 16 float4
            int r = l >> 4, c4 = l & 15;
            *(float4*)(sV + r*68 + c4*4) = *(const float4*)(Vb + (size_t)r*Dc + c4*4);
        }
        __syncthreads();

        #pragma unroll 4
        for (int t = 0; t < 64; t += 4) {
            float4 a0 = *(const float4*)(sA + ty*68 + t);
            float4 a1 = *(const float4*)(sA + (ty + 16)*68 + t);
            #pragma unroll
            for (int k = 0; k < 4; k++) {
                float4 v = *(const float4*)(sV + (t + k)*68 + 4*tx);
                float s0v = (k==0)?a0.x:(k==1)?a0.y:(k==2)?a0.z:a0.w;
                float s1v = (k==0)?a1.x:(k==1)?a1.y:(k==2)?a1.z:a1.w;
                acc0.x += s0v*v.x; acc0.y += s0v*v.y; acc0.z += s0v*v.z; acc0.w += s0v*v.w;
                acc1.x += s1v*v.x; acc1.y += s1v*v.y; acc1.z += s1v*v.z; acc1.w += s1v*v.w;
            }
        }
    }

    *(float4*)(O + (size_t)ty*Dc + 4*tx)      = acc0;
    *(float4*)(O + (size_t)(ty+16)*Dc + 4*tx) = acc1;
}

// ============================================================
extern "C" void kernel_launch(void* const* d_in, const int* in_sizes, int n_in,
                              void* d_out, int out_size) {
    const float* Q  = (const float*)d_in[0];
    const float* K  = (const float*)d_in[1];
    const float* V  = (const float*)d_in[2];
    const float* rp = (const float*)d_in[3];
    const int*   em = (const int*)  d_in[4];
    float* out = (float*)d_out;

    const int smem_score = (2*64*132 + 64*68 + 64) * 4;   // ~85 KB
    const int smem_out   = (32*68 + 64*68) * 4;           // ~26 KB
    cudaFuncSetAttribute(k_score, cudaFuncAttributeMaxDynamicSharedMemorySize, smem_score);
    cudaFuncSetAttribute(k_out,   cudaFuncAttributeMaxDynamicSharedMemorySize, smem_out);

    k_top2   <<<1, 32>>>(rp);
    k_zero   <<<(Bc*Sc*Dc)/(256*4), 256>>>(out);
    k_score  <<<dim3(Sc/64, Bc, Ec), 256, smem_score>>>(Q, K, em);
    k_combine<<<Bc*Sc, 256>>>(em);
    k_out    <<<dim3(Bc, Sc/32, 4), 256, smem_out>>>(V, out);
}

// round 7
// speedup vs baseline: 2.5124x; 1.4469x over previous
#include <cuda_runtime.h>
#include <cuda_bf16.h>
#include <math.h>

#define Bc 4
#define Sc 1024
#define Dc 1024
#define Ec 8
#define DEc 128
#define SCALEF (1.0f/32.0f)   // 1/sqrt(1024)
#define QPITCH 136            // bf16 row pitch (conflict-free fragment loads)

// -------- scratch (static __device__, allocation-free) --------
__device__ float g_S[(size_t)Ec*Bc*Sc*Sc];   // 134 MB unnormalized exp scores
__device__ float g_L[Ec*Bc*Sc];              // row sumexp
__device__ float g_attn[(size_t)Bc*Sc*Sc];   // 16 MB combined attention
__device__ int   g_slot[Bc][2];              // compacted top-2 expert ids

// ---- bf16 helpers ----
__device__ __forceinline__ unsigned pkbf2(float a, float b) {
    __nv_bfloat162 t = __floats2bfloat162_rn(a, b);
    return *(unsigned*)&t;
}
__device__ __forceinline__ void split2(float x, float y,
                                       unsigned &hi, unsigned &lo) {
    __nv_bfloat16 hx = __float2bfloat16(x), hy = __float2bfloat16(y);
    float rx = x - __bfloat162float(hx), ry = y - __bfloat162float(hy);
    __nv_bfloat162 h; h.x = hx; h.y = hy;
    hi = *(unsigned*)&h;
    lo = pkbf2(rx, ry);
}
__device__ __forceinline__ void mma_bf16(float acc[4],
                                         unsigned a0, unsigned a1, unsigned a2, unsigned a3,
                                         unsigned b0, unsigned b1) {
    asm volatile(
        "mma.sync.aligned.m16n8k16.row.col.f32.bf16.bf16.f32 "
        "{%0,%1,%2,%3}, {%4,%5,%6,%7}, {%8,%9}, {%0,%1,%2,%3};"
        : "+f"(acc[0]), "+f"(acc[1]), "+f"(acc[2]), "+f"(acc[3])
        : "r"(a0), "r"(a1), "r"(a2), "r"(a3), "r"(b0), "r"(b1));
}

// ============================================================
// K0: top-2 expert selection (first-occurrence ties, like lax.top_k)
// ============================================================
__global__ void k_top2(const float* __restrict__ rp) {
    int b = threadIdx.x;
    if (b >= Bc) return;
    int i1 = 0; float v1 = rp[b*Ec];
    for (int e = 1; e < Ec; e++) {
        float v = rp[b*Ec + e];
        if (v > v1) { v1 = v; i1 = e; }
    }
    int i2 = -1; float v2 = -INFINITY;
    for (int e = 0; e < Ec; e++) {
        if (e == i1) continue;
        float v = rp[b*Ec + e];
        if (v > v2) { v2 = v; i2 = e; }
    }
    g_slot[b][0] = i1;
    g_slot[b][1] = i2;
}

// ============================================================
// Kz: zero the whole output (unselected expert slices stay zero).
// ============================================================
__global__ void k_zero(float* __restrict__ out) {
    size_t i = ((size_t)blockIdx.x*256 + threadIdx.x)*4;
    *(float4*)(out + i) = make_float4(0.f, 0.f, 0.f, 0.f);
}

// ============================================================
// K1: scores via bf16-split tensor-core MMA (3 products ~ fp32 exact).
// p = exp(QK/32) (no max subtraction: scores ~N(0,0.125), safe).
// grid (S/64, B, E), 256 threads = 8 warps.
// warp w: rows 16*(w>>1), cols 32*(w&1); m16n8k16 fragments loaded
// directly from smem (canonical maps; pitch 136 -> conflict-free).
// ============================================================
__global__ void k_score(const float* __restrict__ Qg, const float* __restrict__ Kg,
                        const int* __restrict__ em) {
    const int e = blockIdx.z, b = blockIdx.y, s0 = blockIdx.x * 64;
    if (em[e*Bc + b] == 0) return;

    extern __shared__ char smraw[];
    __nv_bfloat16* sQh = (__nv_bfloat16*)smraw;        // 64*136
    __nv_bfloat16* sQl = sQh + 64*QPITCH;
    __nv_bfloat16* sKh = sQl + 64*QPITCH;
    __nv_bfloat16* sKl = sKh + 64*QPITCH;
    float* sS  = (float*)(sKl + 64*QPITCH);            // 64*68
    float* sLp = sS + 64*68;                           // 2*64

    const int tid = threadIdx.x;
    const int w = tid >> 5, lane = tid & 31;
    const int g = lane >> 2, tig = lane & 3;
    const int rb = (w >> 1) * 16, nb = (w & 1) * 32;

    // load + split Q tile [64 x 128]
    const float* Qb = Qg + ((size_t)b*Sc + s0)*Dc + e*DEc;
    for (int l = tid; l < 2048; l += 256) {
        int r = l >> 5, c = (l & 31) * 4;
        float4 v = *(const float4*)(Qb + (size_t)r*Dc + c);
        unsigned h01, l01, h23, l23;
        split2(v.x, v.y, h01, l01);
        split2(v.z, v.w, h23, l23);
        *(uint2*)(sQh + r*QPITCH + c) = make_uint2(h01, h23);
        *(uint2*)(sQl + r*QPITCH + c) = make_uint2(l01, l23);
    }

    float rs0 = 0.f, rs1 = 0.f;   // row sums (rows rb+g, rb+g+8), persist
    float* Srow = g_S + (((size_t)e*Bc + b)*Sc + s0)*Sc;

    for (int t0 = 0; t0 < Sc; t0 += 64) {
        __syncthreads();
        const float* Kb = Kg + ((size_t)b*Sc + t0)*Dc + e*DEc;
        for (int l = tid; l < 2048; l += 256) {
            int r = l >> 5, c = (l & 31) * 4;
            float4 v = *(const float4*)(Kb + (size_t)r*Dc + c);
            unsigned h01, l01, h23, l23;
            split2(v.x, v.y, h01, l01);
            split2(v.z, v.w, h23, l23);
            *(uint2*)(sKh + r*QPITCH + c) = make_uint2(h01, h23);
            *(uint2*)(sKl + r*QPITCH + c) = make_uint2(l01, l23);
        }
        __syncthreads();

        float acc[4][4] = {};
        #pragma unroll
        for (int kc = 0; kc < 8; kc++) {
            const int k0 = kc*16 + tig*2;
            unsigned ah0 = *(unsigned*)(sQh + (rb+g  )*QPITCH + k0);
            unsigned ah1 = *(unsigned*)(sQh + (rb+g+8)*QPITCH + k0);
            unsigned ah2 = *(unsigned*)(sQh + (rb+g  )*QPITCH + k0 + 8);
            unsigned ah3 = *(unsigned*)(sQh + (rb+g+8)*QPITCH + k0 + 8);
            unsigned al0 = *(unsigned*)(sQl + (rb+g  )*QPITCH + k0);
            unsigned al1 = *(unsigned*)(sQl + (rb+g+8)*QPITCH + k0);
            unsigned al2 = *(unsigned*)(sQl + (rb+g  )*QPITCH + k0 + 8);
            unsigned al3 = *(unsigned*)(sQl + (rb+g+8)*QPITCH + k0 + 8);
            #pragma unroll
            for (int ns = 0; ns < 4; ns++) {
                const int n = nb + ns*8 + g;
                unsigned bh0 = *(unsigned*)(sKh + n*QPITCH + k0);
                unsigned bh1 = *(unsigned*)(sKh + n*QPITCH + k0 + 8);
                unsigned bl0 = *(unsigned*)(sKl + n*QPITCH + k0);
                unsigned bl1 = *(unsigned*)(sKl + n*QPITCH + k0 + 8);
                mma_bf16(acc[ns], ah0, ah1, ah2, ah3, bh0, bh1);
                mma_bf16(acc[ns], ah0, ah1, ah2, ah3, bl0, bl1);
                mma_bf16(acc[ns], al0, al1, al2, al3, bh0, bh1);
            }
        }

        // epilogue: exp, row-sum accumulate, stage to sS
        #pragma unroll
        for (int ns = 0; ns < 4; ns++) {
            float p0 = __expf(acc[ns][0]*SCALEF);
            float p1 = __expf(acc[ns][1]*SCALEF);
            float p2 = __expf(acc[ns][2]*SCALEF);
            float p3 = __expf(acc[ns][3]*SCALEF);
            rs0 += p0 + p1;
            rs1 += p2 + p3;
            const int col = nb + ns*8 + tig*2;
            *(float2*)(sS + (rb+g  )*68 + col) = make_float2(p0, p1);
            *(float2*)(sS + (rb+g+8)*68 + col) = make_float2(p2, p3);
        }
        __syncthreads();

        // coalesced copy-out
        for (int l = tid; l < 1024; l += 256) {
            int r = l >> 4, c4 = l & 15;
            *(float4*)(Srow + (size_t)r*Sc + t0 + c4*4) = *(const float4*)(sS + r*68 + c4*4);
        }
    }

    // final row sums: reduce over tig, then over the warp pair
    rs0 += __shfl_xor_sync(0xffffffffu, rs0, 1);
    rs0 += __shfl_xor_sync(0xffffffffu, rs0, 2);
    rs1 += __shfl_xor_sync(0xffffffffu, rs1, 1);
    rs1 += __shfl_xor_sync(0xffffffffu, rs1, 2);
    if (tig == 0) {
        sLp[(w & 1)*64 + rb + g]     = rs0;
        sLp[(w & 1)*64 + rb + g + 8] = rs1;
    }
    __syncthreads();
    if (tid < 64)
        g_L[(e*Bc + b)*Sc + s0 + tid] = sLp[tid] + sLp[64 + tid];
}

// ============================================================
// K2: attn[b,s,:] = sum_e mask[e,b] * g_S[e,b,s,:] / L[e,b,s]
// ============================================================
__global__ void k_combine(const int* __restrict__ em) {
    const int bs = blockIdx.x;
    const int b = bs >> 10, s = bs & 1023;
    const int tid = threadIdx.x;

    float4 acc = make_float4(0.f, 0.f, 0.f, 0.f);
    #pragma unroll
    for (int e = 0; e < Ec; e++) {
        if (em[e*Bc + b] == 0) continue;
        int eb = e*Bc + b;
        float invL = 1.0f / g_L[(size_t)eb*Sc + s];
        float4 v = *(const float4*)(g_S + (((size_t)eb*Sc + s)*Sc) + tid*4);
        acc.x += v.x*invL; acc.y += v.y*invL;
        acc.z += v.z*invL; acc.w += v.w*invL;
    }
    *(float4*)(g_attn + ((size_t)b*Sc + s)*Sc + tid*4) = acc;
}

// ============================================================
// K3: out = attn @ V-slice for SELECTED experts only (compacted grid).
// 32-row x 64-col tile, thread = 2 rows x 4 cols. grid (B, S/32, 4).
// ============================================================
__global__ void k_out(const float* __restrict__ Vg, float* __restrict__ out) {
    const int b = blockIdx.x, s0 = blockIdx.y*32;
    const int slot = blockIdx.z >> 1, half = blockIdx.z & 1;
    const int e = g_slot[b][slot];
    const int col0 = e*DEc + half*64;
    float* O = out + ((size_t)b*Sc + s0)*Dc + col0;
    const int tid = threadIdx.x;

    extern __shared__ float smo[];
    float* sA = smo;            // 32 rows x 68 (t index)
    float* sV = smo + 32*68;    // 64 t x 68 (col index)

    const int tx = tid & 15, ty = tid >> 4;
    float4 acc0 = make_float4(0.f,0.f,0.f,0.f);
    float4 acc1 = make_float4(0.f,0.f,0.f,0.f);

    for (int t0 = 0; t0 < Sc; t0 += 64) {
        __syncthreads();
        const float* Ab = g_attn + ((size_t)b*Sc + s0)*Sc + t0;
        for (int l = tid; l < 512; l += 256) {
            int r = l >> 4, c4 = l & 15;
            *(float4*)(sA + r*68 + c4*4) = *(const float4*)(Ab + (size_t)r*Sc + c4*4);
        }
        const float* Vb = Vg + ((size_t)b*Sc + t0)*Dc + col0;
        for (int l = tid; l < 1024; l += 256) {
            int r = l >> 4, c4 = l & 15;
            *(float4*)(sV + r*68 + c4*4) = *(const float4*)(Vb + (size_t)r*Dc + c4*4);
        }
        __syncthreads();

        #pragma unroll 4
        for (int t = 0; t < 64; t += 4) {
            float4 a0 = *(const float4*)(sA + ty*68 + t);
            float4 a1 = *(const float4*)(sA + (ty + 16)*68 + t);
            #pragma unroll
            for (int k = 0; k < 4; k++) {
                float4 v = *(const float4*)(sV + (t + k)*68 + 4*tx);
                float s0v = (k==0)?a0.x:(k==1)?a0.y:(k==2)?a0.z:a0.w;
                float s1v = (k==0)?a1.x:(k==1)?a1.y:(k==2)?a1.z:a1.w;
                acc0.x += s0v*v.x; acc0.y += s0v*v.y; acc0.z += s0v*v.z; acc0.w += s0v*v.w;
                acc1.x += s1v*v.x; acc1.y += s1v*v.y; acc1.z += s1v*v.z; acc1.w += s1v*v.w;
            }
        }
    }

    *(float4*)(O + (size_t)ty*Dc + 4*tx)      = acc0;
    *(float4*)(O + (size_t)(ty+16)*Dc + 4*tx) = acc1;
}

// ============================================================
extern "C" void kernel_launch(void* const* d_in, const int* in_sizes, int n_in,
                              void* d_out, int out_size) {
    const float* Q  = (const float*)d_in[0];
    const float* K  = (const float*)d_in[1];
    const float* V  = (const float*)d_in[2];
    const float* rp = (const float*)d_in[3];
    const int*   em = (const int*)  d_in[4];
    float* out = (float*)d_out;

    const int smem_score = 4*64*QPITCH*2 + (64*68 + 2*64)*4;  // 87552 B
    const int smem_out   = (32*68 + 64*68) * 4;               // ~26 KB
    cudaFuncSetAttribute(k_score, cudaFuncAttributeMaxDynamicSharedMemorySize, smem_score);
    cudaFuncSetAttribute(k_out,   cudaFuncAttributeMaxDynamicSharedMemorySize, smem_out);

    k_top2   <<<1, 32>>>(rp);
    k_zero   <<<(Bc*Sc*Dc)/(256*4), 256>>>(out);
    k_score  <<<dim3(Sc/64, Bc, Ec), 256, smem_score>>>(Q, K, em);
    k_combine<<<Bc*Sc, 256>>>(em);
    k_out    <<<dim3(Bc, Sc/32, 4), 256, smem_out>>>(V, out);
}

// round 9
// speedup vs baseline: 2.8477x; 1.1335x over previous
#include <cuda_runtime.h>
#include <cuda_bf16.h>
#include <math.h>

#define Bc 4
#define Sc 1024
#define Dc 1024
#define Ec 8
#define DEc 128
#define SCALEF (1.0f/32.0f)   // 1/sqrt(1024)
#define QPITCH 136            // bf16 row pitch in k_score (conflict-free)
#define OPITCH 72             // bf16 row pitch in k_out (conflict-free: 36g%32=4g)

// -------- scratch (static __device__, allocation-free) --------
__device__ float g_S[(size_t)Ec*Bc*Sc*Sc];           // 134 MB unnormalized exp scores
__device__ float g_L[Ec*Bc*Sc];                      // row sumexp
__device__ __nv_bfloat16 g_Ah[(size_t)Bc*Sc*Sc];     // 8 MB attn hi
__device__ __nv_bfloat16 g_Al[(size_t)Bc*Sc*Sc];     // 8 MB attn lo
__device__ __nv_bfloat16 g_vt_h[Bc*2*DEc*Sc];        // 2 MB V^T hi  [b][slot][col][t]
__device__ __nv_bfloat16 g_vt_l[Bc*2*DEc*Sc];        // 2 MB V^T lo
__device__ int   g_slot[Bc][2];                      // compacted top-2 expert ids

// ---- bf16 helpers ----
__device__ __forceinline__ unsigned pkbf2(float a, float b) {
    __nv_bfloat162 t = __floats2bfloat162_rn(a, b);
    return *(unsigned*)&t;
}
__device__ __forceinline__ void split2(float x, float y,
                                       unsigned &hi, unsigned &lo) {
    __nv_bfloat16 hx = __float2bfloat16(x), hy = __float2bfloat16(y);
    float rx = x - __bfloat162float(hx), ry = y - __bfloat162float(hy);
    __nv_bfloat162 h; h.x = hx; h.y = hy;
    hi = *(unsigned*)&h;
    lo = pkbf2(rx, ry);
}
__device__ __forceinline__ void split1(float x, __nv_bfloat16 &hi, __nv_bfloat16 &lo) {
    hi = __float2bfloat16(x);
    lo = __float2bfloat16(x - __bfloat162float(hi));
}
__device__ __forceinline__ void mma_bf16(float acc[4],
                                         unsigned a0, unsigned a1, unsigned a2, unsigned a3,
                                         unsigned b0, unsigned b1) {
    asm volatile(
        "mma.sync.aligned.m16n8k16.row.col.f32.bf16.bf16.f32 "
        "{%0,%1,%2,%3}, {%4,%5,%6,%7}, {%8,%9}, {%0,%1,%2,%3};"
        : "+f"(acc[0]), "+f"(acc[1]), "+f"(acc[2]), "+f"(acc[3])
        : "r"(a0), "r"(a1), "r"(a2), "r"(a3), "r"(b0), "r"(b1));
}

// ============================================================
// K0: top-2 expert selection (first-occurrence ties, like lax.top_k)
// ============================================================
__global__ void k_top2(const float* __restrict__ rp) {
    int b = threadIdx.x;
    if (b >= Bc) return;
    int i1 = 0; float v1 = rp[b*Ec];
    for (int e = 1; e < Ec; e++) {
        float v = rp[b*Ec + e];
        if (v > v1) { v1 = v; i1 = e; }
    }
    int i2 = -1; float v2 = -INFINITY;
    for (int e = 0; e < Ec; e++) {
        if (e == i1) continue;
        float v = rp[b*Ec + e];
        if (v > v2) { v2 = v; i2 = e; }
    }
    g_slot[b][0] = i1;
    g_slot[b][1] = i2;
}

// ============================================================
// Kz: zero the whole output (unselected expert slices stay zero).
// ============================================================
__global__ void k_zero(float* __restrict__ out) {
    size_t i = ((size_t)blockIdx.x*256 + threadIdx.x)*4;
    *(float4*)(out + i) = make_float4(0.f, 0.f, 0.f, 0.f);
}

// ============================================================
// Kv: V-slice -> transposed bf16 hi/lo [b][slot][col][t].
// grid (B*2, 16), 256 threads. smem transpose for coalesced I/O.
// ============================================================
__global__ void k_vprep(const float* __restrict__ Vg) {
    const int bs = blockIdx.x;            // b*2 + slot
    const int b = bs >> 1, slot = bs & 1;
    const int e = g_slot[b][slot];
    const int t0 = blockIdx.y * 64;
    const int tid = threadIdx.x;

    __shared__ __nv_bfloat16 sh[128*OPITCH];
    __shared__ __nv_bfloat16 sl[128*OPITCH];

    const float* Vb = Vg + ((size_t)b*Sc + t0)*Dc + e*DEc;
    for (int l = tid; l < 2048; l += 256) {       // 64 t x 32 float4
        int t = l >> 5, c4 = (l & 31)*4;
        float4 v = *(const float4*)(Vb + (size_t)t*Dc + c4);
        __nv_bfloat16 h, lo;
        split1(v.x, h, lo); sh[(c4  )*OPITCH + t] = h; sl[(c4  )*OPITCH + t] = lo;
        split1(v.y, h, lo); sh[(c4+1)*OPITCH + t] = h; sl[(c4+1)*OPITCH + t] = lo;
        split1(v.z, h, lo); sh[(c4+2)*OPITCH + t] = h; sl[(c4+2)*OPITCH + t] = lo;
        split1(v.w, h, lo); sh[(c4+3)*OPITCH + t] = h; sl[(c4+3)*OPITCH + t] = lo;
    }
    __syncthreads();
    __nv_bfloat16* Dh = g_vt_h + ((size_t)bs*DEc)*Sc + t0;
    __nv_bfloat16* Dl = g_vt_l + ((size_t)bs*DEc)*Sc + t0;
    for (int l = tid; l < 2048; l += 256) {       // 128 col x 16 uint2 (4 t each)
        int col = l >> 4, tq = (l & 15)*4;
        *(uint2*)(Dh + (size_t)col*Sc + tq) = *(uint2*)(sh + col*OPITCH + tq);
        *(uint2*)(Dl + (size_t)col*Sc + tq) = *(uint2*)(sl + col*OPITCH + tq);
    }
}

// ============================================================
// K1: scores via bf16-split tensor-core MMA (validated R7).
// ============================================================
__global__ void k_score(const float* __restrict__ Qg, const float* __restrict__ Kg,
                        const int* __restrict__ em) {
    const int e = blockIdx.z, b = blockIdx.y, s0 = blockIdx.x * 64;
    if (em[e*Bc + b] == 0) return;

    extern __shared__ char smraw[];
    __nv_bfloat16* sQh = (__nv_bfloat16*)smraw;        // 64*136
    __nv_bfloat16* sQl = sQh + 64*QPITCH;
    __nv_bfloat16* sKh = sQl + 64*QPITCH;
    __nv_bfloat16* sKl = sKh + 64*QPITCH;
    float* sS  = (float*)(sKl + 64*QPITCH);            // 64*68
    float* sLp = sS + 64*68;                           // 2*64

    const int tid = threadIdx.x;
    const int w = tid >> 5, lane = tid & 31;
    const int g = lane >> 2, tig = lane & 3;
    const int rb = (w >> 1) * 16, nb = (w & 1) * 32;

    const float* Qb = Qg + ((size_t)b*Sc + s0)*Dc + e*DEc;
    for (int l = tid; l < 2048; l += 256) {
        int r = l >> 5, c = (l & 31) * 4;
        float4 v = *(const float4*)(Qb + (size_t)r*Dc + c);
        unsigned h01, l01, h23, l23;
        split2(v.x, v.y, h01, l01);
        split2(v.z, v.w, h23, l23);
        *(uint2*)(sQh + r*QPITCH + c) = make_uint2(h01, h23);
        *(uint2*)(sQl + r*QPITCH + c) = make_uint2(l01, l23);
    }

    float rs0 = 0.f, rs1 = 0.f;
    float* Srow = g_S + (((size_t)e*Bc + b)*Sc + s0)*Sc;

    for (int t0 = 0; t0 < Sc; t0 += 64) {
        __syncthreads();
        const float* Kb = Kg + ((size_t)b*Sc + t0)*Dc + e*DEc;
        for (int l = tid; l < 2048; l += 256) {
            int r = l >> 5, c = (l & 31) * 4;
            float4 v = *(const float4*)(Kb + (size_t)r*Dc + c);
            unsigned h01, l01, h23, l23;
            split2(v.x, v.y, h01, l01);
            split2(v.z, v.w, h23, l23);
            *(uint2*)(sKh + r*QPITCH + c) = make_uint2(h01, h23);
            *(uint2*)(sKl + r*QPITCH + c) = make_uint2(l01, l23);
        }
        __syncthreads();

        float acc[4][4] = {};
        #pragma unroll
        for (int kc = 0; kc < 8; kc++) {
            const int k0 = kc*16 + tig*2;
            unsigned ah0 = *(unsigned*)(sQh + (rb+g  )*QPITCH + k0);
            unsigned ah1 = *(unsigned*)(sQh + (rb+g+8)*QPITCH + k0);
            unsigned ah2 = *(unsigned*)(sQh + (rb+g  )*QPITCH + k0 + 8);
            unsigned ah3 = *(unsigned*)(sQh + (rb+g+8)*QPITCH + k0 + 8);
            unsigned al0 = *(unsigned*)(sQl + (rb+g  )*QPITCH + k0);
            unsigned al1 = *(unsigned*)(sQl + (rb+g+8)*QPITCH + k0);
            unsigned al2 = *(unsigned*)(sQl + (rb+g  )*QPITCH + k0 + 8);
            unsigned al3 = *(unsigned*)(sQl + (rb+g+8)*QPITCH + k0 + 8);
            #pragma unroll
            for (int ns = 0; ns < 4; ns++) {
                const int n = nb + ns*8 + g;
                unsigned bh0 = *(unsigned*)(sKh + n*QPITCH + k0);
                unsigned bh1 = *(unsigned*)(sKh + n*QPITCH + k0 + 8);
                unsigned bl0 = *(unsigned*)(sKl + n*QPITCH + k0);
                unsigned bl1 = *(unsigned*)(sKl + n*QPITCH + k0 + 8);
                mma_bf16(acc[ns], ah0, ah1, ah2, ah3, bh0, bh1);
                mma_bf16(acc[ns], ah0, ah1, ah2, ah3, bl0, bl1);
                mma_bf16(acc[ns], al0, al1, al2, al3, bh0, bh1);
            }
        }

        #pragma unroll
        for (int ns = 0; ns < 4; ns++) {
            float p0 = __expf(acc[ns][0]*SCALEF);
            float p1 = __expf(acc[ns][1]*SCALEF);
            float p2 = __expf(acc[ns][2]*SCALEF);
            float p3 = __expf(acc[ns][3]*SCALEF);
            rs0 += p0 + p1;
            rs1 += p2 + p3;
            const int col = nb + ns*8 + tig*2;
            *(float2*)(sS + (rb+g  )*68 + col) = make_float2(p0, p1);
            *(float2*)(sS + (rb+g+8)*68 + col) = make_float2(p2, p3);
        }
        __syncthreads();

        for (int l = tid; l < 1024; l += 256) {
            int r = l >> 4, c4 = l & 15;
            *(float4*)(Srow + (size_t)r*Sc + t0 + c4*4) = *(const float4*)(sS + r*68 + c4*4);
        }
    }

    rs0 += __shfl_xor_sync(0xffffffffu, rs0, 1);
    rs0 += __shfl_xor_sync(0xffffffffu, rs0, 2);
    rs1 += __shfl_xor_sync(0xffffffffu, rs1, 1);
    rs1 += __shfl_xor_sync(0xffffffffu, rs1, 2);
    if (tig == 0) {
        sLp[(w & 1)*64 + rb + g]     = rs0;
        sLp[(w & 1)*64 + rb + g + 8] = rs1;
    }
    __syncthreads();
    if (tid < 64)
        g_L[(e*Bc + b)*Sc + s0 + tid] = sLp[tid] + sLp[64 + tid];
}

// ============================================================
// K2: attn = sum_e mask*p/L, emitted as split bf16 hi/lo.
// ============================================================
__global__ void k_combine(const int* __restrict__ em) {
    const int bs = blockIdx.x;
    const int b = bs >> 10, s = bs & 1023;
    const int tid = threadIdx.x;

    float4 acc = make_float4(0.f, 0.f, 0.f, 0.f);
    #pragma unroll
    for (int e = 0; e < Ec; e++) {
        if (em[e*Bc + b] == 0) continue;
        int eb = e*Bc + b;
        float invL = 1.0f / g_L[(size_t)eb*Sc + s];
        float4 v = *(const float4*)(g_S + (((size_t)eb*Sc + s)*Sc) + tid*4);
        acc.x += v.x*invL; acc.y += v.y*invL;
        acc.z += v.z*invL; acc.w += v.w*invL;
    }
    unsigned h01, l01, h23, l23;
    split2(acc.x, acc.y, h01, l01);
    split2(acc.z, acc.w, h23, l23);
    size_t base = ((size_t)b*Sc + s)*Sc + tid*4;
    *(uint2*)(g_Ah + base) = make_uint2(h01, h23);
    *(uint2*)(g_Al + base) = make_uint2(l01, l23);
}

// ============================================================
// K3: out = attn @ V-slice via bf16-split MMA. grid (B, 16, 2 slots),
// 256 thr = 8 warps (4 row x 2 col), 64x128 out tile, K-chunks of 64.
// ============================================================
__global__ void k_out(float* __restrict__ out) {
    const int b = blockIdx.x, s0 = blockIdx.y*64, slot = blockIdx.z;
    const int e = g_slot[b][slot];
    const int bs = b*2 + slot;

    extern __shared__ __nv_bfloat16 smb[];
    __nv_bfloat16* sAh = smb;                  // 64*72
    __nv_bfloat16* sAl = sAh + 64*OPITCH;
    __nv_bfloat16* sVh = sAl + 64*OPITCH;      // 128*72
    __nv_bfloat16* sVl = sVh + 128*OPITCH;

    const int tid = threadIdx.x;
    const int w = tid >> 5, lane = tid & 31;
    const int g = lane >> 2, tig = lane & 3;
    const int rb = (w & 3) * 16, nb = (w >> 2) * 64;

    float acc[8][4] = {};

    for (int t0 = 0; t0 < Sc; t0 += 64) {
        __syncthreads();
        const __nv_bfloat16* Abh = g_Ah + ((size_t)b*Sc + s0)*Sc + t0;
        const __nv_bfloat16* Abl = g_Al + ((size_t)b*Sc + s0)*Sc + t0;
        for (int l = tid; l < 1024; l += 256) {        // 64 rows x 16 uint2
            int r = l >> 4, c = (l & 15)*4;
            *(uint2*)(sAh + r*OPITCH + c) = *(const uint2*)(Abh + (size_t)r*Sc + c);
            *(uint2*)(sAl + r*OPITCH + c) = *(const uint2*)(Abl + (size_t)r*Sc + c);
        }
        const __nv_bfloat16* Vbh = g_vt_h + ((size_t)bs*DEc)*Sc + t0;
        const __nv_bfloat16* Vbl = g_vt_l + ((size_t)bs*DEc)*Sc + t0;
        for (int l = tid; l < 2048; l += 256) {        // 128 cols x 16 uint2
            int col = l >> 4, c = (l & 15)*4;
            *(uint2*)(sVh + col*OPITCH + c) = *(const uint2*)(Vbh + (size_t)col*Sc + c);
            *(uint2*)(sVl + col*OPITCH + c) = *(const uint2*)(Vbl + (size_t)col*Sc + c);
        }
        __syncthreads();

        #pragma unroll
        for (int ks = 0; ks < 4; ks++) {
            const int k0 = ks*16 + tig*2;
            unsigned ah0 = *(unsigned*)(sAh + (rb+g  )*OPITCH + k0);
            unsigned ah1 = *(unsigned*)(sAh + (rb+g+8)*OPITCH + k0);
            unsigned ah2 = *(unsigned*)(sAh + (rb+g  )*OPITCH + k0 + 8);
            unsigned ah3 = *(unsigned*)(sAh + (rb+g+8)*OPITCH + k0 + 8);
            unsigned al0 = *(unsigned*)(sAl + (rb+g  )*OPITCH + k0);
            unsigned al1 = *(unsigned*)(sAl + (rb+g+8)*OPITCH + k0);
            unsigned al2 = *(unsigned*)(sAl + (rb+g  )*OPITCH + k0 + 8);
            unsigned al3 = *(unsigned*)(sAl + (rb+g+8)*OPITCH + k0 + 8);
            #pragma unroll
            for (int ns = 0; ns < 8; ns++) {
                const int n = nb + ns*8 + g;
                unsigned bh0 = *(unsigned*)(sVh + n*OPITCH + k0);
                unsigned bh1 = *(unsigned*)(sVh + n*OPITCH + k0 + 8);
                unsigned bl0 = *(unsigned*)(sVl + n*OPITCH + k0);
                unsigned bl1 = *(unsigned*)(sVl + n*OPITCH + k0 + 8);
                mma_bf16(acc[ns], ah0, ah1, ah2, ah3, bh0, bh1);
                mma_bf16(acc[ns], ah0, ah1, ah2, ah3, bl0, bl1);
                mma_bf16(acc[ns], al0, al1, al2, al3, bh0, bh1);
            }
        }
    }

    float* O = out + ((size_t)b*Sc + s0)*Dc + e*DEc;
    #pragma unroll
    for (int ns = 0; ns < 8; ns++) {
        const int nc = nb + ns*8 + tig*2;
        *(float2*)(O + (size_t)(rb+g  )*Dc + nc) = make_float2(acc[ns][0], acc[ns][1]);
        *(float2*)(O + (size_t)(rb+g+8)*Dc + nc) = make_float2(acc[ns][2], acc[ns][3]);
    }
}

// ============================================================
extern "C" void kernel_launch(void* const* d_in, const int* in_sizes, int n_in,
                              void* d_out, int out_size) {
    const float* Q  = (const float*)d_in[0];
    const float* K  = (const float*)d_in[1];
    const float* V  = (const float*)d_in[2];
    const float* rp = (const float*)d_in[3];
    const int*   em = (const int*)  d_in[4];
    float* out = (float*)d_out;

    const int smem_score = 4*64*QPITCH*2 + (64*68 + 2*64)*4;  // 87552 B
    const int smem_out   = (2*64 + 2*128)*OPITCH*2;           // 55296 B
    cudaFuncSetAttribute(k_score, cudaFuncAttributeMaxDynamicSharedMemorySize, smem_score);
    cudaFuncSetAttribute(k_out,   cudaFuncAttributeMaxDynamicSharedMemorySize, smem_out);

    k_top2   <<<1, 32>>>(rp);
    k_zero   <<<(Bc*Sc*Dc)/(256*4), 256>>>(out);
    k_vprep  <<<dim3(Bc*2, 16), 256>>>(V);
    k_score  <<<dim3(Sc/64, Bc, Ec), 256, smem_score>>>(Q, K, em);
    k_combine<<<Bc*Sc, 256>>>(em);
    k_out    <<<dim3(Bc, Sc/64, 2), 256, smem_out>>>(out);
}